// round 11
// baseline (speedup 1.0000x reference)
#include <cuda_runtime.h>

#define B_    4
#define C_    32
#define H_    128
#define W_    256
#define CR_   85
#define HW_   (H_*W_)        // 32768
#define CHW_  (C_*HW_)       // 1048576
#define WW_   (W_*W_)        // 65536
#define BHWW_ (B_*H_*WW_)    // 33554432
#define XN_   (B_*CHW_)      // 4194304
#define STR_  34             // padded row stride for smem q/k (17 ull: conflict-free LDS.64)

typedef unsigned long long ull;

// Per-warp interleaved schedule: SCHED[w*8+n] = tile_code (it*8+jt, d=0 frame)
// | 0x80 if compute tile. Alternating copy/compute per warp.
__constant__ unsigned char SCHED[64] = {
    //  n=0     n=1     n=2     n=3     n=4     n=5     n=6     n=7
       1,   128+0,     2,   128+9,     3,  128+18,     4,  128+27,   // w0
    128+36,     5,  128+45,     6,  128+54,     7,  128+63,    10,   // w1
      11,   128+8,    12,  128+17,    13,  128+26,    14,    15,     // w2
    128+35,    19,  128+44,    20,  128+53,    21,    22,    23,     // w3
      28,  128+62,    29,  128+16,    30,  128+25,    31,    32,     // w4
    128+34,    37,  128+43,    38,  128+52,    39,    40,    41,     // w5
      46,  128+61,    47,  128+24,    48,  128+33,    49,    50,     // w6
    128+42,    55,  128+51,    56,  128+60,    57,    58,    59      // w7
};

// ---- packed f32x2 helpers (Blackwell sm_103a) ----
__device__ __forceinline__ ull pack2(float lo, float hi) {
    ull r;
    asm("mov.b64 %0, {%1, %2};" : "=l"(r) : "f"(lo), "f"(hi));
    return r;
}
__device__ __forceinline__ void fma2(ull &d, ull a, ull b) {
    asm("fma.rn.f32x2 %0, %1, %2, %0;" : "+l"(d) : "l"(a), "l"(b));
}
__device__ __forceinline__ ull add2(ull a, ull b) {
    ull r;
    asm("add.rn.f32x2 %0, %1, %2;" : "=l"(r) : "l"(a), "l"(b));
    return r;
}
__device__ __forceinline__ float sum2(ull a) {
    float lo, hi;
    asm("mov.b64 {%0, %1}, %2;" : "=f"(lo), "=f"(hi) : "l"(a));
    return lo + hi;
}

extern "C" __global__ void __launch_bounds__(256, 3)
pab_kernel(const float* __restrict__ x_left, const float* __restrict__ x_right,
           const float* __restrict__ cost,
           const float* __restrict__ qw, const float* __restrict__ qb,
           const float* __restrict__ qg, const float* __restrict__ qbe,
           const float* __restrict__ qm, const float* __restrict__ qv,
           const float* __restrict__ kw, const float* __restrict__ kb,
           const float* __restrict__ kg, const float* __restrict__ kbe,
           const float* __restrict__ km, const float* __restrict__ kv,
           float* __restrict__ out)
{
    extern __shared__ float sm[];
    float* qA   = sm;            // [256][34]
    float* kA   = sm + 8704;     // [256][34]
    float* wbuf = sm + 17408;    // [1024]: q-weights, then k-weights, then score staging

    const int tid  = threadIdx.x;
    const int warp = tid >> 5;
    const int lane = tid & 31;
    const int bx   = blockIdx.x;
    const int d    = bx & 1;
    const int bh   = bx >> 1;
    const int b    = bh >> 7;
    const int h    = bh & 127;

    // ---- per-lane BN-folded biases (channel = lane), shared later via shfl ----
    float my_bq, my_bk;
    {
        const float sq = qg[lane] * rsqrtf(qv[lane] + 1e-5f);
        const float sk = kg[lane] * rsqrtf(kv[lane] + 1e-5f);
        my_bq = qb[lane] * sq + qbe[lane] - qm[lane] * sq;
        my_bk = kb[lane] * sk + kbe[lane] - km[lane] * sk;
    }

    // ---- phase A: q-weights into wbuf ----
    for (int t = tid; t < 1024; t += 256) {
        const int o = t >> 5;
        wbuf[t] = qw[t] * (qg[o] * rsqrtf(qv[o] + 1e-5f));
    }
    __syncthreads();

    // ---- load x for the q side, emit x*2, pack ----
    const long base = (long)b * CHW_ + (long)h * W_ + tid;
    ull x2[16];
    {
        const float* xq = (d ? x_right : x_left) + base;
        float xv[32];
        #pragma unroll
        for (int c = 0; c < 32; c++) xv[c] = xq[(long)c * HW_];
        float* ox = out + (d ? XN_ : 0) + base;
        #pragma unroll
        for (int c = 0; c < 32; c++) __stcs(ox + (long)c * HW_, 2.0f * xv[c]);
        #pragma unroll
        for (int c2 = 0; c2 < 16; c2++) x2[c2] = pack2(xv[2*c2], xv[2*c2+1]);
    }
    // q projection
    #pragma unroll
    for (int o = 0; o < 32; o++) {
        ull a0 = 0ull, a1 = 0ull;
        const ull* wr = (const ull*)(wbuf + o * 32);
        #pragma unroll
        for (int c2 = 0; c2 < 16; c2 += 2) {
            fma2(a0, wr[c2],   x2[c2]);
            fma2(a1, wr[c2+1], x2[c2+1]);
        }
        qA[tid * STR_ + o] = sum2(add2(a0, a1)) + __shfl_sync(0xffffffffu, my_bq, o);
    }
    __syncthreads();

    // ---- phase B: k-weights into wbuf ----
    for (int t = tid; t < 1024; t += 256) {
        const int o = t >> 5;
        wbuf[t] = kw[t] * (kg[o] * rsqrtf(kv[o] + 1e-5f));
    }
    __syncthreads();

    // ---- load x for the k side (other image), pack, project ----
    {
        const float* xk = (d ? x_left : x_right) + base;
        float xv[32];
        #pragma unroll
        for (int c = 0; c < 32; c++) xv[c] = xk[(long)c * HW_];
        #pragma unroll
        for (int c2 = 0; c2 < 16; c2++) x2[c2] = pack2(xv[2*c2], xv[2*c2+1]);
    }
    #pragma unroll
    for (int o = 0; o < 32; o++) {
        ull a0 = 0ull, a1 = 0ull;
        const ull* wr = (const ull*)(wbuf + o * 32);
        #pragma unroll
        for (int c2 = 0; c2 < 16; c2 += 2) {
            fma2(a0, wr[c2],   x2[c2]);
            fma2(a1, wr[c2+1], x2[c2+1]);
        }
        kA[tid * STR_ + o] = sum2(add2(a0, a1)) + __shfl_sync(0xffffffffu, my_bk, o);
    }
    __syncthreads();   // wbuf now free -> becomes score staging

    // ---- banded attention + cost stream ----
    const float inv_c = 1.0f / 32.0f;
    const float* cbase = cost + (size_t)d * BHWW_ + (size_t)(b * H_ + h) * WW_;
    float*       obase = out  + (d ? (2*XN_ + BHWW_) : (2*XN_)) + (size_t)(b * H_ + h) * WW_;
    const int r0 = lane >> 3;           // 0..3
    const int c4 = (lane & 7) << 2;     // 0,4,...,28
    float* sw = wbuf + (warp << 7);     // 128 floats per warp (4-row chunk staging)

    #pragma unroll 1
    for (int n = 0; n < 8; n++) {
        const int e = SCHED[(warp << 3) + n];
        const int code = e & 63;
        int it = code >> 3, jt = code & 7;
        if (d) { const int tmp = it; it = jt; jt = tmp; }
        const float* cpt = cbase + (size_t)(it * 32) * W_ + (jt << 5);
        float*       opt = obase + (size_t)(it * 32) * W_ + (jt << 5);

        if (e & 128) {
            // ---- band tile: k row in regs, q broadcast from smem ----
            const int jj = (jt << 5) + lane;
            ull k2[16];
            {
                const ull* p = (const ull*)(kA + jj * STR_);
                #pragma unroll
                for (int t = 0; t < 16; t++) k2[t] = p[t];
            }
            float4 cur = __ldcs((const float4*)(cpt + (size_t)r0 * W_ + c4));

            #pragma unroll 1
            for (int cc = 0; cc < 8; cc++) {        // 4-row chunks
                const int row = (cc << 2) + r0;
                float4 nxt = cur;
                if (cc < 7)
                    nxt = __ldcs((const float4*)(cpt + (size_t)(row + 4) * W_ + c4));
                #pragma unroll
                for (int rr = 0; rr < 4; rr++) {
                    const int ii = (it << 5) + (cc << 2) + rr;
                    const ull* qrow = (const ull*)(qA + ii * STR_);
                    ull a0 = 0ull, a1 = 0ull;
                    #pragma unroll
                    for (int c2 = 0; c2 < 16; c2 += 2) {
                        fma2(a0, qrow[c2],   k2[c2]);
                        fma2(a1, qrow[c2+1], k2[c2+1]);
                    }
                    const float s = sum2(add2(a0, a1)) * inv_c;
                    const int df = d ? (jj - ii) : (ii - jj);
                    sw[(rr << 5) + ((((lane >> 2) ^ rr) & 7) << 2) + (lane & 3)] =
                        ((unsigned)df < (unsigned)CR_) ? s : 0.0f;
                }
                __syncwarp();
                const float4 s0 = *(const float4*)(sw + (r0 << 5) + ((((lane & 7) ^ r0) & 7) << 2));
                __syncwarp();
                float4 o4;
                o4.x = cur.x + s0.x; o4.y = cur.y + s0.y;
                o4.z = cur.z + s0.z; o4.w = cur.w + s0.w;
                __stcs((float4*)(opt + (size_t)row * W_ + c4), o4);
                cur = nxt;
            }
        } else {
            // ---- pure copy tile: 8 LDG.128 in flight per lane ----
            float4 v[8];
            #pragma unroll
            for (int t = 0; t < 8; t++)
                v[t] = __ldcs((const float4*)(cpt + (size_t)((t << 2) + r0) * W_ + c4));
            #pragma unroll
            for (int t = 0; t < 8; t++)
                __stcs((float4*)(opt + (size_t)((t << 2) + r0) * W_ + c4), v[t]);
        }
    }
}

extern "C" void kernel_launch(void* const* d_in, const int* in_sizes, int n_in,
                              void* d_out, int out_size)
{
    (void)in_sizes; (void)n_in; (void)out_size;
    // qA 34816 + kA 34816 + wbuf 4096 = 73728 bytes -> 3 CTAs/SM
    const int smem_bytes = 73728;
    cudaFuncSetAttribute(pab_kernel, cudaFuncAttributeMaxDynamicSharedMemorySize, smem_bytes);
    pab_kernel<<<2 * B_ * H_, 256, smem_bytes>>>(
        (const float*)d_in[0],  (const float*)d_in[1],  (const float*)d_in[2],
        (const float*)d_in[3],  (const float*)d_in[4],  (const float*)d_in[5],
        (const float*)d_in[6],  (const float*)d_in[7],  (const float*)d_in[8],
        (const float*)d_in[9],  (const float*)d_in[10], (const float*)d_in[11],
        (const float*)d_in[12], (const float*)d_in[13], (const float*)d_in[14],
        (float*)d_out);
}